// round 1
// baseline (speedup 1.0000x reference)
#include <cuda_runtime.h>

// ShiftedConv2d_25872882991120
//
// Analytic collapse of the reference:
//   _roll_mask keeps ONLY the wrap-around region (i < s), and the padded
//   source rows it pulls from (134 - sh + i) land inside real data (<=127)
//   only when sh == 7 and i == 0. Hence the rolled/masked tensor is nonzero
//   solely when shifts[s] == (7,7), at (0,0), value tens[b,c,127,127].
//   A VALID 7x7 cross-correlation of that single point gives
//     out[b, c*16+s, 0, 0] = tens[b,c,127,127] * filters[s,0,0,0]
//   and zero everywhere else.
//
// So: one store-bound pass writing 64 MiB of zeros with the <=4096 nonzero
// elements computed inline. Pure DRAM-write roofline (~9-10 us floor).

#define B_   8
#define C_   32
#define S_   16
#define HW_  (128 * 128)              // 16384 floats per output plane
#define OUT_ELEMS (B_ * C_ * S_ * HW_) // 16,777,216
#define OUT_V4    (OUT_ELEMS / 4)      // 4,194,304 float4 stores
#define THREADS   256

__global__ void __launch_bounds__(THREADS)
shifted_conv_collapse_kernel(const float* __restrict__ tens,
                             const float* __restrict__ filters,
                             const int*   __restrict__ shifts,
                             float4* __restrict__ out)
{
    unsigned idx = blockIdx.x * THREADS + threadIdx.x;   // grid sized exactly
    float4 v = make_float4(0.f, 0.f, 0.f, 0.f);

    // Each output plane is 16384 floats = 4096 float4. Only the float4 at
    // plane offset 0 (covering x = 0..3 of row y = 0) can hold a nonzero.
    if ((idx & 4095u) == 0u) {
        unsigned ch = idx >> 12;           // ch = b*512 + c*16 + s
        unsigned s  = ch & 15u;
        int sh0 = shifts[2u * s];
        int sh1 = shifts[2u * s + 1u];
        if (sh0 == 7 && sh1 == 7) {
            unsigned c = (ch >> 4) & 31u;
            unsigned b = ch >> 9;
            unsigned n = b * C_ + c;
            float xv = tens[(n * 128u + 127u) * 128u + 127u];
            v.x = xv * filters[s * 49u];   // filters[s,0,0,0]
        }
    }
    out[idx] = v;   // STG.128, fully coalesced streaming write
}

extern "C" void kernel_launch(void* const* d_in, const int* in_sizes, int n_in,
                              void* d_out, int out_size)
{
    const float* tens    = (const float*)d_in[0];
    const float* filters = (const float*)d_in[1];
    const int*   shifts  = (const int*)d_in[2];
    float4*      out     = (float4*)d_out;

    (void)in_sizes; (void)n_in; (void)out_size;

    // 4,194,304 float4 / 256 threads = 16384 blocks, exact cover.
    shifted_conv_collapse_kernel<<<OUT_V4 / THREADS, THREADS>>>(
        tens, filters, shifts, out);
}